// round 2
// baseline (speedup 1.0000x reference)
#include <cuda_runtime.h>

// RCLoss: mean((Gram_c(pred_patches) - Gram_c(target_patches))^2)
// Decomposed into 13 cross-correlation difference maps + gather/centering/reduce.

#define BATCH 4
#define CH    256
#define H     96
#define W     96
#define ND    13      // unique patch-offset vectors (dy,dx): dy=0:dx 0..2, dy=1,2: dx -2..2
#define HP    94
#define WP    94

// scratch: D_d(b,y,x) = sum_c [ p(c,y,x)p(c,y+dy,x+dx) - t(c,y,x)t(c,y+dy,x+dx) ]
__device__ float g_D[BATCH * ND * H * W];

// ---------------------------------------------------------------------------
__global__ void zero_kernel(float* __restrict__ out, int out_size) {
    int i = blockIdx.x * blockDim.x + threadIdx.x;
    const int total = BATCH * ND * H * W;
    if (i < total) g_D[i] = 0.f;
    if (i < out_size) out[i] = 0.f;
}

// ---------------------------------------------------------------------------
// Kernel A: correlation-difference maps.
// Tile: 32 px wide x 16 px tall per block, 4 px per thread -> block (8,16)=128 thr.
// Channel split: 4 chunks of 64 channels per (tile,batch); results atomicAdd'ed.
#define TY   16
#define TXP  32
#define PXT  4
#define NTX  8
#define SC   4        // channels staged in smem at a time
#define CCHUNK 64
#define SMW  37       // padded pitch (36 cols used) -> conflict-free
#define SMH  18       // TY + 2 halo rows

__global__ __launch_bounds__(128, 4)
void corr_kernel(const float* __restrict__ pred, const float* __restrict__ targ) {
    __shared__ float sm[2][SC][SMH * SMW];

    const int tx  = threadIdx.x;            // 0..7
    const int ty  = threadIdx.y;            // 0..15
    const int tid = ty * NTX + tx;
    const int gx0 = blockIdx.x * TXP;
    const int gy0 = blockIdx.y * TY;
    const int b   = blockIdx.z >> 2;
    const int c0  = (blockIdx.z & 3) * CCHUNK;

    float acc[ND][PXT];
    #pragma unroll
    for (int d = 0; d < ND; d++)
        #pragma unroll
        for (int i = 0; i < PXT; i++) acc[d][i] = 0.f;

    const int y  = gy0 + ty;        // this thread's output row (always < 96)
    const int cc = tx * PXT + 2;    // smem col of this thread's first pixel

    for (int cs = 0; cs < CCHUNK; cs += SC) {
        __syncthreads();
        // cooperative stage: 2 tensors x SC channels x 18 rows x 36 cols
        for (int i = tid; i < 2 * SC * SMH * 36; i += 128) {
            int t    = i / (SC * SMH * 36);
            int rem  = i - t * (SC * SMH * 36);
            int c    = rem / (SMH * 36);
            int rem2 = rem - c * (SMH * 36);
            int rr   = rem2 / 36;
            int col  = rem2 - rr * 36;
            int gy   = gy0 + rr;
            int gxx  = gx0 - 2 + col;
            float v = 0.f;
            if (gy < H && gxx >= 0 && gxx < W) {
                const float* base = t ? targ : pred;
                v = base[(((b * CH) + (c0 + cs + c)) * H + gy) * W + gxx];
            }
            sm[t][c][rr * SMW + col] = v;
        }
        __syncthreads();

        #pragma unroll
        for (int c = 0; c < SC; c++) {
            #pragma unroll
            for (int t = 0; t < 2; t++) {
                const float* s = sm[t][c];
                float v0[6], v1[8], v2[8];
                const float* r0 = s + ty * SMW + cc;
                #pragma unroll
                for (int j = 0; j < 6; j++) v0[j] = r0[j];
                const float* r1 = s + (ty + 1) * SMW + cc - 2;
                #pragma unroll
                for (int j = 0; j < 8; j++) v1[j] = r1[j];
                const float* r2 = s + (ty + 2) * SMW + cc - 2;
                #pragma unroll
                for (int j = 0; j < 8; j++) v2[j] = r2[j];

                #pragma unroll
                for (int i = 0; i < PXT; i++) {
                    float ctr = (t == 0) ? v0[i] : -v0[i];   // pred adds, target subtracts
                    acc[0][i]  = fmaf(ctr, v0[i],     acc[0][i]);   // d=(0,0)
                    acc[1][i]  = fmaf(ctr, v0[i + 1], acc[1][i]);   // d=(0,1)
                    acc[2][i]  = fmaf(ctr, v0[i + 2], acc[2][i]);   // d=(0,2)
                    acc[3][i]  = fmaf(ctr, v1[i],     acc[3][i]);   // d=(1,-2)
                    acc[4][i]  = fmaf(ctr, v1[i + 1], acc[4][i]);   // d=(1,-1)
                    acc[5][i]  = fmaf(ctr, v1[i + 2], acc[5][i]);   // d=(1,0)
                    acc[6][i]  = fmaf(ctr, v1[i + 3], acc[6][i]);   // d=(1,1)
                    acc[7][i]  = fmaf(ctr, v1[i + 4], acc[7][i]);   // d=(1,2)
                    acc[8][i]  = fmaf(ctr, v2[i],     acc[8][i]);   // d=(2,-2)
                    acc[9][i]  = fmaf(ctr, v2[i + 1], acc[9][i]);   // d=(2,-1)
                    acc[10][i] = fmaf(ctr, v2[i + 2], acc[10][i]);  // d=(2,0)
                    acc[11][i] = fmaf(ctr, v2[i + 3], acc[11][i]);  // d=(2,1)
                    acc[12][i] = fmaf(ctr, v2[i + 4], acc[12][i]);  // d=(2,2)
                }
            }
        }
    }

    const int x0 = gx0 + tx * PXT;
    #pragma unroll
    for (int d = 0; d < ND; d++)
        #pragma unroll
        for (int i = 0; i < PXT; i++)
            atomicAdd(&g_D[((b * ND + d) * H + y) * W + (x0 + i)], acc[d][i]);
}

// ---------------------------------------------------------------------------
// Kernel B: per-patch gather of S = Sp - St from D maps, centering, squared sum.
// G[k,l] = S[k,l] - (r_k + r_l)/9 + T/81 ;  loss = mean over B*94*94*81 of G^2.
__global__ __launch_bounds__(256)
void loss_kernel(float* __restrict__ out) {
    const int x = blockIdx.x * 32 + threadIdx.x;
    const int y = blockIdx.y * 8 + threadIdx.y;
    const int b = blockIdx.z;

    float lp = 0.f;
    if (x < WP && y < HP) {
        float S[9][9];
        const float* Db = g_D + b * ND * H * W;
        #pragma unroll
        for (int k = 0; k < 9; k++) {
            const int ky = k / 3, kx = k % 3;
            #pragma unroll
            for (int l = k; l < 9; l++) {
                const int ly = l / 3, lx = l % 3;
                const int dy = ly - ky, dx = lx - kx;           // dy>=0; dy==0 => dx>=0
                const int didx = (dy == 0) ? dx : (dy == 1 ? 5 + dx : 10 + dx);
                float v = Db[(didx * H + (y + ky)) * W + (x + kx)];
                S[k][l] = v;
                S[l][k] = v;
            }
        }
        float r[9];
        float T = 0.f;
        #pragma unroll
        for (int k = 0; k < 9; k++) {
            float s = 0.f;
            #pragma unroll
            for (int l = 0; l < 9; l++) s += S[k][l];
            r[k] = s;
            T += s;
        }
        const float i9 = 1.f / 9.f;
        const float Tc = T * (1.f / 81.f);
        #pragma unroll
        for (int k = 0; k < 9; k++)
            #pragma unroll
            for (int l = 0; l < 9; l++) {
                float g = S[k][l] - (r[k] + r[l]) * i9 + Tc;
                lp = fmaf(g, g, lp);
            }
    }

    // block reduction: each row of the block is one warp (blockDim = 32x8)
    #pragma unroll
    for (int o = 16; o > 0; o >>= 1)
        lp += __shfl_down_sync(0xffffffffu, lp, o);
    __shared__ float ws[8];
    if (threadIdx.x == 0) ws[threadIdx.y] = lp;
    __syncthreads();
    if (threadIdx.x == 0 && threadIdx.y == 0) {
        float s = 0.f;
        #pragma unroll
        for (int w = 0; w < 8; w++) s += ws[w];
        const float NORM = 1.f / (float)(BATCH * HP * WP * 81);  // 1/2862864
        atomicAdd(out, s * NORM);
    }
}

// ---------------------------------------------------------------------------
extern "C" void kernel_launch(void* const* d_in, const int* in_sizes, int n_in,
                              void* d_out, int out_size) {
    const float* pred = (const float*)d_in[0];
    const float* targ = (const float*)d_in[1];
    float* out = (float*)d_out;

    {   // zero scratch + output
        const int total = BATCH * ND * H * W;
        zero_kernel<<<(total + 255) / 256, 256>>>(out, out_size);
    }
    {   // correlation-difference maps
        dim3 grid(W / TXP, H / TY, BATCH * 4);   // (3, 6, 16)
        dim3 block(NTX, TY);                     // (8, 16) = 128
        corr_kernel<<<grid, block>>>(pred, targ);
    }
    {   // gather + centering + MSE reduce
        dim3 grid(3, 12, BATCH);                 // covers 94x94 patches
        dim3 block(32, 8);
        loss_kernel<<<grid, block>>>(out);
    }
}

// round 3
// speedup vs baseline: 2.4253x; 2.4253x over previous
#include <cuda_runtime.h>

// RCLoss = mean((Gram_c(pred_patches) - Gram_c(target_patches))^2), 3x3 patches, C=256.
// Decomposition: centered Gram is linear in the raw Gram; raw-Gram entries are shifted
// samples of 13 unique cross-correlation maps D_d = sum_c (p*p_shift - t*t_shift).
// Kernel A computes D (per channel-chunk slices, cp.async double-buffered).
// Kernel B gathers per-patch S, centers, squares, reduces to per-block partials.
// Kernel C reduces partials.

#define BATCH   4
#define CH      256
#define H       96
#define W       96
#define HW      (H*W)
#define ND      13
#define HP      94
#define WP      94
#define NCHUNK  8
#define CCHUNK  32            // CH / NCHUNK

#define SMH        18         // 16 tile rows + 2 halo
#define SMCOLS     36         // 32 tile cols + 2+2 halo
#define PITCH      37         // conflict-free pitch
#define IMG_STRIDE (SMH*PITCH)        // 666 floats per image tile
#define BUF_FLOATS (2*IMG_STRIDE)     // pred+targ per buffer
#define STAGE_ELEMS (2*SMH*SMCOLS)    // 1296 staged floats per stage
#define NJ         11                 // ceil(1296/128)

#define LOSS_BLOCKS (3*12*4)          // 144

__device__ float g_D[BATCH*NCHUNK*ND*HW];   // per-chunk correlation-difference slices
__device__ float g_part[LOSS_BLOCKS];

// ---------------------------------------------------------------------------
__device__ __forceinline__ void cp4(unsigned saddr, const float* g) {
    asm volatile("cp.async.ca.shared.global [%0], [%1], 4;\n" :: "r"(saddr), "l"(g));
}
__device__ __forceinline__ void cp_commit() {
    asm volatile("cp.async.commit_group;\n" ::: "memory");
}
template<int N> __device__ __forceinline__ void cp_wait() {
    asm volatile("cp.async.wait_group %0;\n" :: "n"(N) : "memory");
}

// ---------------------------------------------------------------------------
// Kernel A: 13 correlation-difference maps, one (batch, channel-chunk) per block.z.
// Tile 32x16 output px, 4 px/thread, block (8,16)=128 threads.
__global__ __launch_bounds__(128, 4)
void corr_kernel(const float* __restrict__ pred, const float* __restrict__ targ) {
    __shared__ float sm[2*BUF_FLOATS];

    const int tx  = threadIdx.x;              // 0..7
    const int ty  = threadIdx.y;              // 0..15
    const int tid = ty*8 + tx;
    const int gx0 = blockIdx.x * 32;
    const int gy0 = blockIdx.y * 16;
    const int b     = blockIdx.z >> 3;
    const int chunk = blockIdx.z & 7;

    const unsigned smbase = (unsigned)__cvta_generic_to_shared(sm);

    // Precompute per-thread staging slots (stage-invariant): smem byte offset,
    // gmem element offset within one channel image, valid + tensor-select masks.
    unsigned sof[NJ];
    int      gof[NJ];
    unsigned vmask = 0, tmask = 0;
    #pragma unroll
    for (int j = 0; j < NJ; j++) {
        int e   = tid + 128*j;
        int t   = (e >= SMH*SMCOLS) ? 1 : 0;
        int e2  = e - t*(SMH*SMCOLS);
        int row = e2 / SMCOLS;
        int col = e2 - row*SMCOLS;
        int gy  = gy0 + row;
        int gx  = gx0 - 2 + col;
        bool inrange = (e < STAGE_ELEMS);
        bool valid   = inrange && (gy < H) && (gx >= 0) && (gx < W);
        sof[j] = (unsigned)((t*IMG_STRIDE + row*PITCH + col) * 4);
        gof[j] = gy*W + gx;
        if (valid) vmask |= 1u << j;
        if (t)     tmask |= 1u << j;
        if (inrange && !valid) {               // zero the halo slots once, both buffers
            sm[sof[j] >> 2]              = 0.f;
            sm[BUF_FLOATS + (sof[j]>>2)] = 0.f;
        }
    }

    const float* pbase = pred + (size_t)(b*CH + chunk*CCHUNK) * HW;
    const float* tbase = targ + (size_t)(b*CH + chunk*CCHUNK) * HW;

    float acc[ND][4];
    #pragma unroll
    for (int d = 0; d < ND; d++)
        #pragma unroll
        for (int i = 0; i < 4; i++) acc[d][i] = 0.f;

    // prologue: stage 0 -> buffer 0
    #pragma unroll
    for (int j = 0; j < NJ; j++)
        if ((vmask >> j) & 1)
            cp4(smbase + sof[j], (((tmask >> j) & 1) ? tbase : pbase) + gof[j]);
    cp_commit();

    const int cc = tx*4 + 2;   // smem col of this thread's first output pixel

    #pragma unroll 1
    for (int s = 0; s < CCHUNK; s++) {
        if (s + 1 < CCHUNK) {
            const float* pb = pbase + (size_t)(s+1)*HW;
            const float* tb = tbase + (size_t)(s+1)*HW;
            const unsigned bofs = (unsigned)(((s+1) & 1) * (BUF_FLOATS*4));
            #pragma unroll
            for (int j = 0; j < NJ; j++)
                if ((vmask >> j) & 1)
                    cp4(smbase + bofs + sof[j], (((tmask >> j) & 1) ? tb : pb) + gof[j]);
            cp_commit();
            cp_wait<1>();
        } else {
            cp_wait<0>();
        }
        __syncthreads();

        const float* buf = sm + (s & 1) * BUF_FLOATS;
        #pragma unroll
        for (int t = 0; t < 2; t++) {
            const float* sI = buf + t*IMG_STRIDE;
            float v0[6], v1[8], v2[8];
            const float* r0 = sI + ty*PITCH + cc;
            #pragma unroll
            for (int j = 0; j < 6; j++) v0[j] = r0[j];
            const float* r1 = sI + (ty+1)*PITCH + cc - 2;
            #pragma unroll
            for (int j = 0; j < 8; j++) v1[j] = r1[j];
            const float* r2 = sI + (ty+2)*PITCH + cc - 2;
            #pragma unroll
            for (int j = 0; j < 8; j++) v2[j] = r2[j];

            #pragma unroll
            for (int i = 0; i < 4; i++) {
                float ctr = t ? -v0[i] : v0[i];       // pred adds, target subtracts
                acc[0][i]  = fmaf(ctr, v0[i],     acc[0][i]);   // (0,0)
                acc[1][i]  = fmaf(ctr, v0[i + 1], acc[1][i]);   // (0,1)
                acc[2][i]  = fmaf(ctr, v0[i + 2], acc[2][i]);   // (0,2)
                acc[3][i]  = fmaf(ctr, v1[i],     acc[3][i]);   // (1,-2)
                acc[4][i]  = fmaf(ctr, v1[i + 1], acc[4][i]);   // (1,-1)
                acc[5][i]  = fmaf(ctr, v1[i + 2], acc[5][i]);   // (1,0)
                acc[6][i]  = fmaf(ctr, v1[i + 3], acc[6][i]);   // (1,1)
                acc[7][i]  = fmaf(ctr, v1[i + 4], acc[7][i]);   // (1,2)
                acc[8][i]  = fmaf(ctr, v2[i],     acc[8][i]);   // (2,-2)
                acc[9][i]  = fmaf(ctr, v2[i + 1], acc[9][i]);   // (2,-1)
                acc[10][i] = fmaf(ctr, v2[i + 2], acc[10][i]);  // (2,0)
                acc[11][i] = fmaf(ctr, v2[i + 3], acc[11][i]);  // (2,1)
                acc[12][i] = fmaf(ctr, v2[i + 4], acc[12][i]);  // (2,2)
            }
        }
        __syncthreads();
    }

    // plain vectorized store into this (b, chunk)'s private slice — no atomics
    float* slice = g_D + (size_t)(b*NCHUNK + chunk) * ND * HW;
    const int y  = gy0 + ty;
    const int x0 = gx0 + tx*4;
    #pragma unroll
    for (int d = 0; d < ND; d++) {
        float4 v = make_float4(acc[d][0], acc[d][1], acc[d][2], acc[d][3]);
        *reinterpret_cast<float4*>(slice + (size_t)(d*H + y)*W + x0) = v;
    }
}

// ---------------------------------------------------------------------------
// Kernel B: gather S (summing NCHUNK slices), center, square, per-block partial.
__global__ __launch_bounds__(256)
void loss_kernel() {
    const int x = blockIdx.x * 32 + threadIdx.x;
    const int y = blockIdx.y * 8  + threadIdx.y;
    const int b = blockIdx.z;

    float lp = 0.f;
    if (x < WP && y < HP) {
        float S[9][9];
        const float* Db = g_D + (size_t)b * NCHUNK * ND * HW;
        #pragma unroll
        for (int k = 0; k < 9; k++) {
            const int ky = k/3, kx = k%3;
            #pragma unroll
            for (int l = k; l < 9; l++) {
                const int ly = l/3, lx = l%3;
                const int dy = ly - ky, dx = lx - kx;      // dy>=0; dy==0 => dx>=0
                const int didx = (dy == 0) ? dx : (dy == 1 ? 5 + dx : 10 + dx);
                const int idx  = (didx*H + (y + ky))*W + (x + kx);
                float v = 0.f;
                #pragma unroll
                for (int c = 0; c < NCHUNK; c++)
                    v += Db[(size_t)c * ND * HW + idx];
                S[k][l] = v;
                S[l][k] = v;
            }
        }
        float r[9], T = 0.f;
        #pragma unroll
        for (int k = 0; k < 9; k++) {
            float s = 0.f;
            #pragma unroll
            for (int l = 0; l < 9; l++) s += S[k][l];
            r[k] = s; T += s;
        }
        const float i9 = 1.f/9.f;
        const float Tc = T * (1.f/81.f);
        #pragma unroll
        for (int k = 0; k < 9; k++)
            #pragma unroll
            for (int l = 0; l < 9; l++) {
                float g = S[k][l] - (r[k] + r[l])*i9 + Tc;
                lp = fmaf(g, g, lp);
            }
    }

    #pragma unroll
    for (int o = 16; o > 0; o >>= 1)
        lp += __shfl_down_sync(0xffffffffu, lp, o);
    __shared__ float ws[8];
    if (threadIdx.x == 0) ws[threadIdx.y] = lp;
    __syncthreads();
    if (threadIdx.x == 0 && threadIdx.y == 0) {
        float s = 0.f;
        #pragma unroll
        for (int w = 0; w < 8; w++) s += ws[w];
        g_part[blockIdx.z*36 + blockIdx.y*3 + blockIdx.x] = s;
    }
}

// ---------------------------------------------------------------------------
// Kernel C: reduce 144 partials -> out[0] (out needs no pre-zero).
__global__ void final_kernel(float* __restrict__ out) {
    const int t = threadIdx.x;
    float v = (t < LOSS_BLOCKS) ? g_part[t] : 0.f;
    #pragma unroll
    for (int o = 16; o > 0; o >>= 1)
        v += __shfl_down_sync(0xffffffffu, v, o);
    __shared__ float ws[8];
    if ((t & 31) == 0) ws[t >> 5] = v;
    __syncthreads();
    if (t == 0) {
        float s = 0.f;
        #pragma unroll
        for (int w = 0; w < 8; w++) s += ws[w];
        out[0] = s * (float)(1.0 / (double)(BATCH * HP * WP * 81));
    }
}

// ---------------------------------------------------------------------------
extern "C" void kernel_launch(void* const* d_in, const int* in_sizes, int n_in,
                              void* d_out, int out_size) {
    const float* pred = (const float*)d_in[0];
    const float* targ = (const float*)d_in[1];
    float* out = (float*)d_out;

    {   // correlation-difference slices
        dim3 grid(3, 6, BATCH * NCHUNK);     // (3,6,32) = 576 blocks
        dim3 block(8, 16);
        corr_kernel<<<grid, block>>>(pred, targ);
    }
    {   // gather + center + partial MSE
        dim3 grid(3, 12, BATCH);
        dim3 block(32, 8);
        loss_kernel<<<grid, block>>>();
    }
    final_kernel<<<1, 256>>>(out);
}

// round 5
// speedup vs baseline: 3.1137x; 1.2838x over previous
#include <cuda_runtime.h>

// RCLoss = mean((Gram_c(pred_patches) - Gram_c(target_patches))^2), 3x3 patches, C=256.
// Centered Gram is linear in raw Gram; raw-Gram entries are shifted samples of 13
// cross-correlation difference maps D_d = sum_c (p*p_shift - t*t_shift).
// Kernel A: D maps, full-width tiles, flat contiguous cp.async staging, depth-3 pipeline.
// Kernel B: per-patch gather + centering + partial MSE. Kernel C: final reduce.

#define BATCH   4
#define CH      256
#define H       96
#define W       96
#define HW      (H*W)
#define ND      13
#define HP      94
#define WP      94
#define NCHUNK  8
#define CCHUNK  32

#define TROWS     8                   // output rows per block
#define SROWS     10                  // staged rows (TROWS + 2)
#define TFLOATS   (SROWS*W)           // 960 floats staged per tensor
#define TVEC      (TFLOATS/4)         // 240 float4 per tensor
#define TSTRIDE   (TFLOATS+8)         // +4 guard front (16B-aligned data) +4 back
#define BUFSTRIDE (2*TSTRIDE)         // pred+targ
#define DEPTH     3

#define LOSS_BLOCKS (3*12*4)

__device__ float g_D[BATCH*NCHUNK*ND*HW];
__device__ float g_part[LOSS_BLOCKS];

__device__ __forceinline__ void cp16(unsigned saddr, const float* g) {
    asm volatile("cp.async.cg.shared.global [%0], [%1], 16;\n" :: "r"(saddr), "l"(g));
}
__device__ __forceinline__ void cp_commit() {
    asm volatile("cp.async.commit_group;\n" ::: "memory");
}
template<int N> __device__ __forceinline__ void cp_wait() {
    asm volatile("cp.async.wait_group %0;\n" :: "n"(N) : "memory");
}

// ---------------------------------------------------------------------------
// Kernel A. grid (12, NCHUNK, BATCH), block (32, 8).
__global__ __launch_bounds__(256, 3)
void corr_kernel(const float* __restrict__ pred, const float* __restrict__ targ) {
    __shared__ float sm[DEPTH * BUFSTRIDE];

    const int lane = threadIdx.x;           // 0..31
    const int ty   = threadIdx.y;           // 0..7  (warp id == row id)
    const int tid  = ty * 32 + lane;
    const int gy0  = blockIdx.x * TROWS;
    const int chunk= blockIdx.y;
    const int b    = blockIdx.z;

    const int avail = (gy0 + SROWS <= H) ? SROWS : (H - gy0);   // 10 or 8

    // Zero rows [avail, SROWS) in all buffers once (their D entries are unused).
    if (avail < SROWS) {
        const int zfl = (SROWS - avail) * W;                    // 192
        for (int i = tid; i < DEPTH * 2 * zfl; i += 256) {
            int buf = i / (2 * zfl);
            int r   = i - buf * (2 * zfl);
            int t   = r / zfl;
            int f   = r - t * zfl;
            sm[buf * BUFSTRIDE + t * TSTRIDE + 4 + avail * W + f] = 0.f;
        }
    }
    __syncthreads();

    // Flat staging: 2*TVEC = 480 float4 slots per stage, 256 threads, 2 slots/thread.
    // slot0: e = tid        -> tensor t0 = (tid >= TVEC), vec index f0 = tid - t0*TVEC
    // slot1: e = tid + 256  -> always tensor 1, vec index f1 = tid + 256 - TVEC
    const int  t0 = (tid >= TVEC) ? 1 : 0;
    const int  f0 = tid - t0 * TVEC;                // 0..239
    const int  f1 = tid + 256 - TVEC;               // 16..271
    const bool m0 = (f0 * 4 < avail * W);
    const bool m1 = (f1 < TVEC) && (f1 * 4 < avail * W);

    const unsigned smbase = (unsigned)__cvta_generic_to_shared(sm);
    const unsigned s0 = (unsigned)((t0 * TSTRIDE + 4 + f0 * 4) * 4);
    const unsigned s1 = (unsigned)((1  * TSTRIDE + 4 + f1 * 4) * 4);

    const size_t cbase = (size_t)(b * CH + chunk * CCHUNK) * HW + (size_t)gy0 * W;
    const float* g0 = (t0 ? targ : pred) + cbase + f0 * 4;
    const float* g1 = targ              + cbase + f1 * 4;

    float acc[ND][3];
    #pragma unroll
    for (int d = 0; d < ND; d++)
        #pragma unroll
        for (int i = 0; i < 3; i++) acc[d][i] = 0.f;

    // prologue: stages 0 .. DEPTH-2
    #pragma unroll
    for (int s = 0; s < DEPTH - 1; s++) {
        const unsigned bo = (unsigned)(s * BUFSTRIDE * 4);
        if (m0) cp16(smbase + bo + s0, g0 + (size_t)s * HW);
        if (m1) cp16(smbase + bo + s1, g1 + (size_t)s * HW);
        cp_commit();
    }

    const int c0 = lane * 3;

    #pragma unroll 1
    for (int s = 0; s < CCHUNK; s++) {
        if (s + DEPTH - 1 < CCHUNK) {
            const int sn = s + DEPTH - 1;
            const unsigned bo = (unsigned)((sn % DEPTH) * BUFSTRIDE * 4);
            if (m0) cp16(smbase + bo + s0, g0 + (size_t)sn * HW);
            if (m1) cp16(smbase + bo + s1, g1 + (size_t)sn * HW);
            cp_commit();
            cp_wait<DEPTH - 1>();
        } else if (s + DEPTH - 1 == CCHUNK) {
            cp_wait<DEPTH - 2>();
        } else {
            cp_wait<0>();
        }
        __syncthreads();

        const float* buf = sm + (s % DEPTH) * BUFSTRIDE;
        #pragma unroll
        for (int t = 0; t < 2; t++) {
            const float* sI = buf + t * TSTRIDE + 4;
            float v0[5], v1[7], v2[7];
            const float* r0 = sI + ty * W + c0;
            #pragma unroll
            for (int j = 0; j < 5; j++) v0[j] = r0[j];
            const float* r1 = sI + (ty + 1) * W + c0 - 2;
            #pragma unroll
            for (int j = 0; j < 7; j++) v1[j] = r1[j];
            const float* r2 = sI + (ty + 2) * W + c0 - 2;
            #pragma unroll
            for (int j = 0; j < 7; j++) v2[j] = r2[j];

            #pragma unroll
            for (int i = 0; i < 3; i++) {
                float ctr = t ? -v0[i] : v0[i];
                acc[0][i]  = fmaf(ctr, v0[i],     acc[0][i]);   // (0,0)
                acc[1][i]  = fmaf(ctr, v0[i + 1], acc[1][i]);   // (0,1)
                acc[2][i]  = fmaf(ctr, v0[i + 2], acc[2][i]);   // (0,2)
                acc[3][i]  = fmaf(ctr, v1[i],     acc[3][i]);   // (1,-2)
                acc[4][i]  = fmaf(ctr, v1[i + 1], acc[4][i]);   // (1,-1)
                acc[5][i]  = fmaf(ctr, v1[i + 2], acc[5][i]);   // (1,0)
                acc[6][i]  = fmaf(ctr, v1[i + 3], acc[6][i]);   // (1,1)
                acc[7][i]  = fmaf(ctr, v1[i + 4], acc[7][i]);   // (1,2)
                acc[8][i]  = fmaf(ctr, v2[i],     acc[8][i]);   // (2,-2)
                acc[9][i]  = fmaf(ctr, v2[i + 1], acc[9][i]);   // (2,-1)
                acc[10][i] = fmaf(ctr, v2[i + 2], acc[10][i]);  // (2,0)
                acc[11][i] = fmaf(ctr, v2[i + 3], acc[11][i]);  // (2,1)
                acc[12][i] = fmaf(ctr, v2[i + 4], acc[12][i]);  // (2,2)
            }
        }
        __syncthreads();
    }

    float* slice = g_D + (size_t)(b * NCHUNK + chunk) * ND * HW;
    const int y = gy0 + ty;
    #pragma unroll
    for (int d = 0; d < ND; d++) {
        float* p = slice + (size_t)(d * H + y) * W + c0;
        p[0] = acc[d][0]; p[1] = acc[d][1]; p[2] = acc[d][2];
    }
}

// ---------------------------------------------------------------------------
// Kernel B: gather S (summing NCHUNK slices), center, square, per-block partial.
__global__ __launch_bounds__(256)
void loss_kernel() {
    const int x = blockIdx.x * 32 + threadIdx.x;
    const int y = blockIdx.y * 8  + threadIdx.y;
    const int b = blockIdx.z;

    float lp = 0.f;
    if (x < WP && y < HP) {
        float S[9][9];
        const float* Db = g_D + (size_t)b * NCHUNK * ND * HW;
        #pragma unroll
        for (int k = 0; k < 9; k++) {
            const int ky = k/3, kx = k%3;
            #pragma unroll
            for (int l = k; l < 9; l++) {
                const int ly = l/3, lx = l%3;
                const int dy = ly - ky, dx = lx - kx;
                const int didx = (dy == 0) ? dx : (dy == 1 ? 5 + dx : 10 + dx);
                const int idx  = (didx*H + (y + ky))*W + (x + kx);
                float v = 0.f;
                #pragma unroll
                for (int c = 0; c < NCHUNK; c++)
                    v += Db[(size_t)c * ND * HW + idx];
                S[k][l] = v;
                S[l][k] = v;
            }
        }
        float r[9], T = 0.f;
        #pragma unroll
        for (int k = 0; k < 9; k++) {
            float s = 0.f;
            #pragma unroll
            for (int l = 0; l < 9; l++) s += S[k][l];
            r[k] = s; T += s;
        }
        const float i9 = 1.f/9.f;
        const float Tc = T * (1.f/81.f);
        #pragma unroll
        for (int k = 0; k < 9; k++)
            #pragma unroll
            for (int l = 0; l < 9; l++) {
                float g = S[k][l] - (r[k] + r[l])*i9 + Tc;
                lp = fmaf(g, g, lp);
            }
    }

    #pragma unroll
    for (int o = 16; o > 0; o >>= 1)
        lp += __shfl_down_sync(0xffffffffu, lp, o);
    __shared__ float ws[8];
    if (threadIdx.x == 0) ws[threadIdx.y] = lp;
    __syncthreads();
    if (threadIdx.x == 0 && threadIdx.y == 0) {
        float s = 0.f;
        #pragma unroll
        for (int w = 0; w < 8; w++) s += ws[w];
        g_part[blockIdx.z*36 + blockIdx.y*3 + blockIdx.x] = s;
    }
}

// ---------------------------------------------------------------------------
__global__ void final_kernel(float* __restrict__ out) {
    const int t = threadIdx.x;
    float v = (t < LOSS_BLOCKS) ? g_part[t] : 0.f;
    #pragma unroll
    for (int o = 16; o > 0; o >>= 1)
        v += __shfl_down_sync(0xffffffffu, v, o);
    __shared__ float ws[8];
    if ((t & 31) == 0) ws[t >> 5] = v;
    __syncthreads();
    if (t == 0) {
        float s = 0.f;
        #pragma unroll
        for (int w = 0; w < 8; w++) s += ws[w];
        out[0] = s * (float)(1.0 / (double)(BATCH * HP * WP * 81));
    }
}

// ---------------------------------------------------------------------------
extern "C" void kernel_launch(void* const* d_in, const int* in_sizes, int n_in,
                              void* d_out, int out_size) {
    const float* pred = (const float*)d_in[0];
    const float* targ = (const float*)d_in[1];
    float* out = (float*)d_out;

    {
        dim3 grid(12, NCHUNK, BATCH);    // 384 blocks
        dim3 block(32, 8);
        corr_kernel<<<grid, block>>>(pred, targ);
    }
    {
        dim3 grid(3, 12, BATCH);
        dim3 block(32, 8);
        loss_kernel<<<grid, block>>>();
    }
    final_kernel<<<1, 256>>>(out);
}

// round 6
// speedup vs baseline: 3.4437x; 1.1060x over previous
#include <cuda_runtime.h>

// RCLoss = mean((Gram_c(pred_patches) - Gram_c(target_patches))^2), 3x3 patches, C=256.
// Centered Gram is linear in raw Gram; raw-Gram entries are shifted samples of 13
// cross-correlation difference maps D_d = sum_c (p*p_shift - t*t_shift).
// A: corr maps (768 small blocks, depth-4 cp.async, 1 barrier/stage).
// B: sum 8 chunk slices -> 1 map. C: per-patch gather+center+MSE partials. D: reduce.

#define BATCH   4
#define CH      256
#define H       96
#define W       96
#define HW      (H*W)
#define ND      13
#define HP      94
#define WP      94
#define NCHUNK  8
#define CCHUNK  32

#define TROWS     4                   // output rows per block
#define SROWS     6                   // staged rows
#define TFLOATS   (SROWS*W)           // 576
#define TVEC      (TFLOATS/4)         // 144 float4 per tensor
#define TSTRIDE   (TFLOATS+8)         // +4 front guard (keeps 16B align) +4 back
#define BUFSTRIDE (2*TSTRIDE)         // 1168
#define DEPTH     4

#define LOSS_BLOCKS (3*12*4)
#define SUM_N4   (BATCH*ND*HW/4)      // 119808 float4s

__device__ float g_D[BATCH*NCHUNK*ND*HW];     // per-chunk slices
__device__ float g_Dsum[BATCH*ND*HW];         // chunk-summed maps (1.9MB, L2-resident)
__device__ float g_part[LOSS_BLOCKS];

__device__ __forceinline__ void cp16(unsigned saddr, const float* g) {
    asm volatile("cp.async.cg.shared.global [%0], [%1], 16;\n" :: "r"(saddr), "l"(g));
}
__device__ __forceinline__ void cp_commit() {
    asm volatile("cp.async.commit_group;\n" ::: "memory");
}
template<int N> __device__ __forceinline__ void cp_wait() {
    asm volatile("cp.async.wait_group %0;\n" :: "n"(N) : "memory");
}

// ---------------------------------------------------------------------------
// Kernel A. grid (24, NCHUNK, BATCH) = 768 blocks, block (32, 4).
__global__ __launch_bounds__(128, 6)
void corr_kernel(const float* __restrict__ pred, const float* __restrict__ targ) {
    __shared__ float sm[DEPTH * BUFSTRIDE];

    const int lane  = threadIdx.x;
    const int ty    = threadIdx.y;            // 0..3, warp == output row
    const int tid   = ty * 32 + lane;
    const int gy0   = blockIdx.x * TROWS;
    const int chunk = blockIdx.y;
    const int b     = blockIdx.z;

    const int avail = (gy0 + SROWS <= H) ? SROWS : (H - gy0);   // 6 or 4

    if (avail < SROWS) {   // zero unused staged rows once in every buffer
        const int zfl = (SROWS - avail) * W;                     // 192
        for (int i = tid; i < DEPTH * 2 * zfl; i += 128) {
            int buf = i / (2 * zfl);
            int r   = i - buf * (2 * zfl);
            int t   = r / zfl;
            int f   = r - t * zfl;
            sm[buf * BUFSTRIDE + t * TSTRIDE + 4 + avail * W + f] = 0.f;
        }
    }

    // Flat staging slots: 2*TVEC = 288 float4 per stage, 128 threads, 3 slots.
    const size_t cbase = (size_t)(b * CH + chunk * CCHUNK) * HW + (size_t)gy0 * W;
    unsigned     sof[3];
    const float* gp[3];
    bool         m[3];
    #pragma unroll
    for (int j = 0; j < 3; j++) {
        int  e = tid + 128 * j;
        int  t = (e >= TVEC) ? 1 : 0;
        int  f = e - t * TVEC;
        m[j]   = (e < 2 * TVEC) && (f * 4 < avail * W);
        sof[j] = (unsigned)((t * TSTRIDE + 4 + f * 4) * 4);
        gp[j]  = (t ? targ : pred) + cbase + f * 4;
    }
    const unsigned smbase = (unsigned)__cvta_generic_to_shared(sm);

    float acc[ND][3];
    #pragma unroll
    for (int d = 0; d < ND; d++)
        #pragma unroll
        for (int i = 0; i < 3; i++) acc[d][i] = 0.f;

    // prologue: groups 0 .. DEPTH-2
    #pragma unroll
    for (int s = 0; s < DEPTH - 1; s++) {
        const unsigned bo = (unsigned)(s * BUFSTRIDE * 4);
        #pragma unroll
        for (int j = 0; j < 3; j++)
            if (m[j]) cp16(smbase + bo + sof[j], gp[j] + (size_t)s * HW);
        cp_commit();
    }

    const int c0 = lane * 3;

    #pragma unroll 1
    for (int s = 0; s < CCHUNK; s++) {
        // need group s complete; pending at entry = groups s .. min(s+DEPTH-2, 31)
        if      (s < CCHUNK - 2) cp_wait<DEPTH - 2>();
        else if (s == CCHUNK - 2) cp_wait<1>();
        else                      cp_wait<0>();
        __syncthreads();

        // issue stage s+DEPTH-1 into buffer (s-1)%DEPTH; safe: ordered after sync(s)
        if (s + DEPTH - 1 < CCHUNK) {
            const int sn = s + DEPTH - 1;
            const unsigned bo = (unsigned)((sn % DEPTH) * BUFSTRIDE * 4);
            #pragma unroll
            for (int j = 0; j < 3; j++)
                if (m[j]) cp16(smbase + bo + sof[j], gp[j] + (size_t)sn * HW);
            cp_commit();
        }

        const float* buf = sm + (s % DEPTH) * BUFSTRIDE;
        #pragma unroll
        for (int t = 0; t < 2; t++) {
            const float* sI = buf + t * TSTRIDE + 4;
            float v0[5], v1[7], v2[7];
            const float* r0 = sI + ty * W + c0;
            #pragma unroll
            for (int j = 0; j < 5; j++) v0[j] = r0[j];
            const float* r1 = sI + (ty + 1) * W + c0 - 2;
            #pragma unroll
            for (int j = 0; j < 7; j++) v1[j] = r1[j];
            const float* r2 = sI + (ty + 2) * W + c0 - 2;
            #pragma unroll
            for (int j = 0; j < 7; j++) v2[j] = r2[j];

            #pragma unroll
            for (int i = 0; i < 3; i++) {
                float ctr = t ? -v0[i] : v0[i];
                acc[0][i]  = fmaf(ctr, v0[i],     acc[0][i]);
                acc[1][i]  = fmaf(ctr, v0[i + 1], acc[1][i]);
                acc[2][i]  = fmaf(ctr, v0[i + 2], acc[2][i]);
                acc[3][i]  = fmaf(ctr, v1[i],     acc[3][i]);
                acc[4][i]  = fmaf(ctr, v1[i + 1], acc[4][i]);
                acc[5][i]  = fmaf(ctr, v1[i + 2], acc[5][i]);
                acc[6][i]  = fmaf(ctr, v1[i + 3], acc[6][i]);
                acc[7][i]  = fmaf(ctr, v1[i + 4], acc[7][i]);
                acc[8][i]  = fmaf(ctr, v2[i],     acc[8][i]);
                acc[9][i]  = fmaf(ctr, v2[i + 1], acc[9][i]);
                acc[10][i] = fmaf(ctr, v2[i + 2], acc[10][i]);
                acc[11][i] = fmaf(ctr, v2[i + 3], acc[11][i]);
                acc[12][i] = fmaf(ctr, v2[i + 4], acc[12][i]);
            }
        }
    }

    float* slice = g_D + (size_t)(b * NCHUNK + chunk) * ND * HW;
    const int y = gy0 + ty;
    #pragma unroll
    for (int d = 0; d < ND; d++) {
        float* p = slice + (size_t)(d * H + y) * W + c0;
        p[0] = acc[d][0]; p[1] = acc[d][1]; p[2] = acc[d][2];
    }
}

// ---------------------------------------------------------------------------
// Kernel B: collapse 8 chunk slices -> g_Dsum. grid 468 x 256 covers SUM_N4 exactly.
__global__ __launch_bounds__(256)
void sum8_kernel() {
    const int i = blockIdx.x * 256 + threadIdx.x;       // float4 index
    const int per_b = ND * HW / 4;                      // 29952
    const int b = i / per_b;
    const int r = i - b * per_b;
    const float4* base = reinterpret_cast<const float4*>(g_D) +
                         (size_t)b * NCHUNK * per_b + r;
    float4 s = make_float4(0.f, 0.f, 0.f, 0.f);
    #pragma unroll
    for (int c = 0; c < NCHUNK; c++) {
        float4 v = base[(size_t)c * per_b];
        s.x += v.x; s.y += v.y; s.z += v.z; s.w += v.w;
    }
    reinterpret_cast<float4*>(g_Dsum)[i] = s;
}

// ---------------------------------------------------------------------------
// Kernel C: gather S from g_Dsum, center, square, per-block partial.
__global__ __launch_bounds__(256)
void loss_kernel() {
    const int x = blockIdx.x * 32 + threadIdx.x;
    const int y = blockIdx.y * 8  + threadIdx.y;
    const int b = blockIdx.z;

    float lp = 0.f;
    if (x < WP && y < HP) {
        float S[9][9];
        const float* Db = g_Dsum + (size_t)b * ND * HW;
        #pragma unroll
        for (int k = 0; k < 9; k++) {
            const int ky = k/3, kx = k%3;
            #pragma unroll
            for (int l = k; l < 9; l++) {
                const int ly = l/3, lx = l%3;
                const int dy = ly - ky, dx = lx - kx;
                const int didx = (dy == 0) ? dx : (dy == 1 ? 5 + dx : 10 + dx);
                float v = Db[(didx*H + (y + ky))*W + (x + kx)];
                S[k][l] = v;
                S[l][k] = v;
            }
        }
        float r[9], T = 0.f;
        #pragma unroll
        for (int k = 0; k < 9; k++) {
            float s = 0.f;
            #pragma unroll
            for (int l = 0; l < 9; l++) s += S[k][l];
            r[k] = s; T += s;
        }
        const float i9 = 1.f/9.f;
        const float Tc = T * (1.f/81.f);
        #pragma unroll
        for (int k = 0; k < 9; k++)
            #pragma unroll
            for (int l = 0; l < 9; l++) {
                float g = S[k][l] - (r[k] + r[l])*i9 + Tc;
                lp = fmaf(g, g, lp);
            }
    }

    #pragma unroll
    for (int o = 16; o > 0; o >>= 1)
        lp += __shfl_down_sync(0xffffffffu, lp, o);
    __shared__ float ws[8];
    if (threadIdx.x == 0) ws[threadIdx.y] = lp;
    __syncthreads();
    if (threadIdx.x == 0 && threadIdx.y == 0) {
        float s = 0.f;
        #pragma unroll
        for (int w = 0; w < 8; w++) s += ws[w];
        g_part[blockIdx.z*36 + blockIdx.y*3 + blockIdx.x] = s;
    }
}

// ---------------------------------------------------------------------------
__global__ void final_kernel(float* __restrict__ out) {
    const int t = threadIdx.x;
    float v = (t < LOSS_BLOCKS) ? g_part[t] : 0.f;
    #pragma unroll
    for (int o = 16; o > 0; o >>= 1)
        v += __shfl_down_sync(0xffffffffu, v, o);
    __shared__ float ws[8];
    if ((t & 31) == 0) ws[t >> 5] = v;
    __syncthreads();
    if (t == 0) {
        float s = 0.f;
        #pragma unroll
        for (int w = 0; w < 8; w++) s += ws[w];
        out[0] = s * (float)(1.0 / (double)(BATCH * HP * WP * 81));
    }
}

// ---------------------------------------------------------------------------
extern "C" void kernel_launch(void* const* d_in, const int* in_sizes, int n_in,
                              void* d_out, int out_size) {
    const float* pred = (const float*)d_in[0];
    const float* targ = (const float*)d_in[1];
    float* out = (float*)d_out;

    {
        dim3 grid(H / TROWS, NCHUNK, BATCH);   // (24, 8, 4) = 768 blocks
        dim3 block(32, TROWS);
        corr_kernel<<<grid, block>>>(pred, targ);
    }
    sum8_kernel<<<SUM_N4 / 256, 256>>>();
    {
        dim3 grid(3, 12, BATCH);
        dim3 block(32, 8);
        loss_kernel<<<grid, block>>>();
    }
    final_kernel<<<1, 256>>>(out);
}